// round 1
// baseline (speedup 1.0000x reference)
#include <cuda_runtime.h>
#include <math.h>
#include <stdint.h>

#define BSZ_ 8
#define LEN_ 8192
#define PDIM 128
#define HDIM 128
#define CH 64
#define NC (LEN_/CH)

// ---------------- scratch (static device globals; no runtime allocs) ----------
__device__ float2 g_Bu[(size_t)BSZ_*LEN_*PDIM];    // 64 MB  (b,l,p) complex
__device__ float2 g_ys[(size_t)BSZ_*LEN_*PDIM];    // 64 MB  (b,l,p) complex
__device__ float4 g_csum[BSZ_*NC*PDIM];            // chunk partial sums (h1r,h1i,h2r,h2i)
__device__ float4 g_cin [BSZ_*NC*PDIM];            // chunk incoming states
__device__ float4 g_M  [PDIM];                     // m11,m12,m21,m22
__device__ float2 g_c  [PDIM];                     // c1 = dt/S, c2 = dt^2/S
__device__ float4 g_Mp [PDIM];                     // M^CH
__device__ float  g_W1 [HDIM*2*PDIM];              // [h][2p+ri]  (GEMM1 weights)
__device__ float  g_W2 [2*PDIM*HDIM];              // [2p+ri][h]  (GEMM2 weights, -Ci folded)

// ---------------- prep: per-p scalars + M^CH + weight repack ------------------
__global__ void prep_kernel(const float* __restrict__ Ad, const float* __restrict__ Gd,
                            const float* __restrict__ dtv,
                            const float* __restrict__ Bin, const float* __restrict__ Cin) {
    int tid = threadIdx.x;
    if (tid < PDIM) {
        int p = tid;
        float dts = 1.0f / (1.0f + expf(-dtv[p]));
        float A   = fmaxf(Ad[p], 0.0f);
        float G   = fmaxf(Gd[p], 0.0f);
        float dt2 = fmaxf(dts*dts, 1e-6f);
        float s   = sqrtf(1.0f + dts*G);
        float alo = (2.0f + dts*G - 2.0f*s) / dt2;
        float ahi = (2.0f + dts*G + 2.0f*s) / dt2;
        float Af  = fminf(fmaxf(A, alo), ahi);
        float S    = 1.0f + dts*G;
        float invS = 1.0f / S;
        float m11 = invS;
        float m12 = -dts*invS*Af;
        float m21 = dts*invS;
        float m22 = 1.0f - dts*dts*invS*Af;
        g_M[p] = make_float4(m11, m12, m21, m22);
        g_c[p] = make_float2(dts*invS, dts*dts*invS);
        // M^CH with CH = 64 = 2^6 by repeated squaring
        float a = m11, b = m12, c = m21, d = m22;
        #pragma unroll
        for (int i = 0; i < 6; i++) {
            float na = a*a + b*c;
            float nb = a*b + b*d;
            float nc = c*a + d*c;
            float nd = c*b + d*d;
            a = na; b = nb; c = nc; d = nd;
        }
        g_Mp[p] = make_float4(a, b, c, d);
    }
    // W1[h][2p+ri] = B[p][h][ri]    (B layout: (P,H,2))
    for (int idx = tid; idx < HDIM*2*PDIM; idx += blockDim.x) {
        int h = idx / (2*PDIM);
        int n = idx % (2*PDIM);
        int p = n >> 1, ri = n & 1;
        g_W1[idx] = Bin[((size_t)p*HDIM + h)*2 + ri];
    }
    // W2[2p+ri][h] = +C[h][p][0] or -C[h][p][1]   (C layout: (H,P,2))
    for (int idx = tid; idx < 2*PDIM*HDIM; idx += blockDim.x) {
        int k = idx / HDIM;
        int h = idx % HDIM;
        int p = k >> 1, ri = k & 1;
        float v = Cin[((size_t)h*PDIM + p)*2 + ri];
        g_W2[idx] = ri ? -v : v;
    }
}

// ---------------- fp32 SIMT GEMM: C[M,N] = A[M,K] @ W[K,N] (+ D*x epilogue) ---
// BM=128, BN=128, BK=32, 256 threads, 8x8 register tiles (split 4+4 interleave)
template<bool EPILOGUE>
__global__ void __launch_bounds__(256)
gemm128_kernel(const float* __restrict__ A, const float* __restrict__ W,
               float* __restrict__ Cout, int M, int N, int K,
               const float* __restrict__ xres, const float* __restrict__ Dvec) {
    const int BM = 128, BN = 128, BK = 32;
    __shared__ float As[BK][BM];   // transposed A tile: [k][m]
    __shared__ float Ws[BK][BN];   // [k][n]

    int tid = threadIdx.x;
    int tx = tid & 15;      // 0..15 -> n groups
    int ty = tid >> 4;      // 0..15 -> m groups
    int bm = blockIdx.y * BM;
    int bn = blockIdx.x * BN;

    float acc[8][8];
    #pragma unroll
    for (int i = 0; i < 8; i++)
        #pragma unroll
        for (int j = 0; j < 8; j++) acc[i][j] = 0.0f;

    for (int k0 = 0; k0 < K; k0 += BK) {
        // load A tile (128 rows x 32 cols), stored transposed into As
        {
            int c4 = tid & 7;       // float4 index within the 32-wide row
            int r0 = tid >> 3;      // 0..31
            #pragma unroll
            for (int rr = 0; rr < 4; rr++) {
                int row = r0 + rr*32;
                float4 v = *(const float4*)&A[(size_t)(bm + row)*K + k0 + c4*4];
                As[c4*4+0][row] = v.x;
                As[c4*4+1][row] = v.y;
                As[c4*4+2][row] = v.z;
                As[c4*4+3][row] = v.w;
            }
        }
        // load W tile (32 rows x 128 cols), direct
        {
            int c4 = tid & 31;      // float4 index in row of 128
            int r0 = tid >> 5;      // 0..7
            #pragma unroll
            for (int rr = 0; rr < 4; rr++) {
                int kr = r0 + rr*8;
                *(float4*)&Ws[kr][c4*4] =
                    *(const float4*)&W[(size_t)(k0 + kr)*N + bn + c4*4];
            }
        }
        __syncthreads();
        #pragma unroll
        for (int k = 0; k < BK; k++) {
            float a[8], b[8];
            *(float4*)&a[0] = *(float4*)&As[k][ty*4];
            *(float4*)&a[4] = *(float4*)&As[k][64 + ty*4];
            *(float4*)&b[0] = *(float4*)&Ws[k][tx*4];
            *(float4*)&b[4] = *(float4*)&Ws[k][64 + tx*4];
            #pragma unroll
            for (int i = 0; i < 8; i++)
                #pragma unroll
                for (int j = 0; j < 8; j++)
                    acc[i][j] += a[i] * b[j];
        }
        __syncthreads();
    }

    #pragma unroll
    for (int i = 0; i < 8; i++) {
        int row = bm + ((i < 4) ? (ty*4 + i) : (64 + ty*4 + i - 4));
        #pragma unroll
        for (int jh = 0; jh < 2; jh++) {
            int col = bn + jh*64 + tx*4;
            float4 r;
            r.x = acc[i][jh*4+0];
            r.y = acc[i][jh*4+1];
            r.z = acc[i][jh*4+2];
            r.w = acc[i][jh*4+3];
            if (EPILOGUE) {
                float4 xv = *(const float4*)&xres[(size_t)row*HDIM + col];
                float4 dv = *(const float4*)&Dvec[col];
                r.x += dv.x * xv.x;
                r.y += dv.y * xv.y;
                r.z += dv.z * xv.z;
                r.w += dv.w * xv.w;
            }
            *(float4*)&Cout[(size_t)row*N + col] = r;
        }
    }
}

// ---------------- scan pass 1: per-chunk partial sums (zero init) -------------
__global__ void scan_partial_kernel() {
    int p = threadIdx.x;
    int c = blockIdx.x;
    int b = blockIdx.y;
    float4 Mv = g_M[p];
    float2 cv = g_c[p];
    float h1r = 0.f, h1i = 0.f, h2r = 0.f, h2i = 0.f;
    size_t base = ((size_t)b*LEN_ + (size_t)c*CH) * PDIM + p;
    #pragma unroll 8
    for (int l = 0; l < CH; l++) {
        float2 bu = g_Bu[base + (size_t)l*PDIM];
        float n1r = Mv.x*h1r + Mv.y*h2r + cv.x*bu.x;
        float n1i = Mv.x*h1i + Mv.y*h2i + cv.x*bu.y;
        float n2r = Mv.z*h1r + Mv.w*h2r + cv.y*bu.x;
        float n2i = Mv.z*h1i + Mv.w*h2i + cv.y*bu.y;
        h1r = n1r; h1i = n1i; h2r = n2r; h2i = n2i;
    }
    g_csum[(b*NC + c)*PDIM + p] = make_float4(h1r, h1i, h2r, h2i);
}

// ---------------- scan pass 2: carry combine across chunks with M^CH ----------
__global__ void scan_carry_kernel() {
    int p = threadIdx.x;
    int b = blockIdx.x;
    float4 Mp = g_Mp[p];
    float h1r = 0.f, h1i = 0.f, h2r = 0.f, h2i = 0.f;
    for (int c = 0; c < NC; c++) {
        int idx = (b*NC + c)*PDIM + p;
        g_cin[idx] = make_float4(h1r, h1i, h2r, h2i);
        float4 s = g_csum[idx];
        float n1r = Mp.x*h1r + Mp.y*h2r + s.x;
        float n1i = Mp.x*h1i + Mp.y*h2i + s.y;
        float n2r = Mp.z*h1r + Mp.w*h2r + s.z;
        float n2i = Mp.z*h1i + Mp.w*h2i + s.w;
        h1r = n1r; h1i = n1i; h2r = n2r; h2i = n2i;
    }
}

// ---------------- scan pass 3: final scan with incoming state, writes ys ------
__global__ void scan_final_kernel() {
    int p = threadIdx.x;
    int c = blockIdx.x;
    int b = blockIdx.y;
    float4 Mv = g_M[p];
    float2 cv = g_c[p];
    float4 hin = g_cin[(b*NC + c)*PDIM + p];
    float h1r = hin.x, h1i = hin.y, h2r = hin.z, h2i = hin.w;
    size_t base = ((size_t)b*LEN_ + (size_t)c*CH) * PDIM + p;
    #pragma unroll 8
    for (int l = 0; l < CH; l++) {
        float2 bu = g_Bu[base + (size_t)l*PDIM];
        float n1r = Mv.x*h1r + Mv.y*h2r + cv.x*bu.x;
        float n1i = Mv.x*h1i + Mv.y*h2i + cv.x*bu.y;
        float n2r = Mv.z*h1r + Mv.w*h2r + cv.y*bu.x;
        float n2i = Mv.z*h1i + Mv.w*h2i + cv.y*bu.y;
        h1r = n1r; h1i = n1i; h2r = n2r; h2i = n2i;
        g_ys[base + (size_t)l*PDIM] = make_float2(h2r, h2i);
    }
}

// ---------------- launch ------------------------------------------------------
extern "C" void kernel_launch(void* const* d_in, const int* in_sizes, int n_in,
                              void* d_out, int out_size) {
    const float* x  = (const float*)d_in[0];
    const float* Ad = (const float*)d_in[1];
    const float* Gd = (const float*)d_in[2];
    const float* dt = (const float*)d_in[3];
    const float* B  = (const float*)d_in[4];
    const float* C  = (const float*)d_in[5];
    const float* D  = (const float*)d_in[6];
    float* out = (float*)d_out;

    void *pBu, *pYs, *pW1, *pW2;
    cudaGetSymbolAddress(&pBu, g_Bu);
    cudaGetSymbolAddress(&pYs, g_ys);
    cudaGetSymbolAddress(&pW1, g_W1);
    cudaGetSymbolAddress(&pW2, g_W2);

    const int M = BSZ_ * LEN_;   // 65536

    prep_kernel<<<1, 256>>>(Ad, Gd, dt, B, C);

    // GEMM1: Bu(M x 256) = x(M x 128) @ W1(128 x 256)
    {
        dim3 grid(256/128, M/128);
        gemm128_kernel<false><<<grid, 256>>>(x, (const float*)pW1, (float*)pBu,
                                             M, 2*PDIM, HDIM, nullptr, nullptr);
    }

    scan_partial_kernel<<<dim3(NC, BSZ_), PDIM>>>();
    scan_carry_kernel<<<BSZ_, PDIM>>>();
    scan_final_kernel<<<dim3(NC, BSZ_), PDIM>>>();

    // GEMM2: out(M x 128) = ys(M x 256) @ W2(256 x 128) + D*x
    {
        dim3 grid(128/128, M/128);
        gemm128_kernel<true><<<grid, 256>>>((const float*)pYs, (const float*)pW2, out,
                                            M, HDIM, 2*PDIM, x, D);
    }
}

// round 4
// speedup vs baseline: 1.7368x; 1.7368x over previous
#include <cuda_runtime.h>
#include <math.h>
#include <stdint.h>

#define BSZ_ 8
#define LEN_ 8192
#define PDIM 128
#define HDIM 128
#define CH 64
#define NC (LEN_/CH)

// ---------------- scratch ----------------------------------------------------
__device__ float2 g_Bu[(size_t)BSZ_*LEN_*PDIM];    // 64 MB  (b,l,p) complex
__device__ float2 g_ys[(size_t)BSZ_*LEN_*PDIM];    // 64 MB  (b,l,p) complex (tf32-rounded)
__device__ float4 g_csum[BSZ_*NC*PDIM];
__device__ float4 g_cin [BSZ_*NC*PDIM];
__device__ float4 g_M  [PDIM];
__device__ float2 g_c  [PDIM];
__device__ float4 g_Mp [PDIM];
__device__ float  g_W1 [2*PDIM*HDIM];              // [n=2p+ri][k=h]  tf32-rounded
__device__ float  g_W2 [HDIM*2*PDIM];              // [n=h][k=2p+ri]  tf32-rounded, sign folded

__device__ __forceinline__ float tf32r(float x) {
    uint32_t u;
    asm("cvt.rna.tf32.f32 %0, %1;" : "=r"(u) : "f"(x));
    return __uint_as_float(u);
}

__device__ __forceinline__ void mma_tf32(float* d, const uint32_t* a, const uint32_t* b) {
    asm volatile(
        "mma.sync.aligned.m16n8k8.row.col.f32.tf32.tf32.f32 "
        "{%0,%1,%2,%3}, {%4,%5,%6,%7}, {%8,%9}, {%0,%1,%2,%3};"
        : "+f"(d[0]), "+f"(d[1]), "+f"(d[2]), "+f"(d[3])
        : "r"(a[0]), "r"(a[1]), "r"(a[2]), "r"(a[3]), "r"(b[0]), "r"(b[1]));
}

// ---------------- prep -------------------------------------------------------
__global__ void prep_kernel(const float* __restrict__ Ad, const float* __restrict__ Gd,
                            const float* __restrict__ dtv,
                            const float* __restrict__ Bin, const float* __restrict__ Cin) {
    int tid = threadIdx.x;
    if (tid < PDIM) {
        int p = tid;
        float dts = 1.0f / (1.0f + expf(-dtv[p]));
        float A   = fmaxf(Ad[p], 0.0f);
        float G   = fmaxf(Gd[p], 0.0f);
        float dt2 = fmaxf(dts*dts, 1e-6f);
        float s   = sqrtf(1.0f + dts*G);
        float alo = (2.0f + dts*G - 2.0f*s) / dt2;
        float ahi = (2.0f + dts*G + 2.0f*s) / dt2;
        float Af  = fminf(fmaxf(A, alo), ahi);
        float S    = 1.0f + dts*G;
        float invS = 1.0f / S;
        float m11 = invS;
        float m12 = -dts*invS*Af;
        float m21 = dts*invS;
        float m22 = 1.0f - dts*dts*invS*Af;
        g_M[p] = make_float4(m11, m12, m21, m22);
        g_c[p] = make_float2(dts*invS, dts*dts*invS);
        float a = m11, b = m12, c = m21, d = m22;
        #pragma unroll
        for (int i = 0; i < 6; i++) {
            float na = a*a + b*c;
            float nb = a*b + b*d;
            float nc = c*a + d*c;
            float nd = c*b + d*d;
            a = na; b = nb; c = nc; d = nd;
        }
        g_Mp[p] = make_float4(a, b, c, d);
    }
    // W1[n=2p+ri][k=h] = B[p][h][ri]   (B layout (P,H,2))
    for (int idx = tid; idx < 2*PDIM*HDIM; idx += blockDim.x) {
        int n = idx / HDIM, h = idx % HDIM;
        int p = n >> 1, ri = n & 1;
        g_W1[idx] = tf32r(Bin[((size_t)p*HDIM + h)*2 + ri]);
    }
    // W2[n=h][k=2p+ri] = +-C[h][p][ri]  (C layout (H,P,2) flat = [h][2p+ri])
    for (int idx = tid; idx < HDIM*2*PDIM; idx += blockDim.x) {
        int k = idx % (2*PDIM);
        float v = Cin[idx];
        g_W2[idx] = tf32r((k & 1) ? -v : v);
    }
}

// ---------------- GEMM1: Bu(M x 256) = x(M x 128) @ W1^T ----------------------
// mma.sync tf32, BM=128, BN=128, full K=128 in smem, 256 threads (8 warps 4x2)
#define PITCH_A 132
__global__ void __launch_bounds__(256, 1)
gemm1_kernel(const float* __restrict__ x) {
    extern __shared__ float smem[];
    float* As = smem;                    // [128][132]
    float* Ws = smem + 128*PITCH_A;      // [128][132]
    int tid = threadIdx.x;
    int wid = tid >> 5, lane = tid & 31;
    int wm = wid >> 1, wn = wid & 1;     // warp tile: rows wm*32, cols wn*64
    int g = lane >> 2, t = lane & 3;     // groupID, thread-in-group
    int bm = blockIdx.y * 128;
    int bn = blockIdx.x * 128;

    // load x tile (tf32-rounded) and W1 tile
    #pragma unroll
    for (int i = 0; i < 16; i++) {
        int flat = i*256 + tid;
        int row = flat >> 5, c4 = flat & 31;
        float4 v = *(const float4*)&x[(size_t)(bm + row)*128 + c4*4];
        v.x = tf32r(v.x); v.y = tf32r(v.y); v.z = tf32r(v.z); v.w = tf32r(v.w);
        *(float4*)&As[row*PITCH_A + c4*4] = v;
    }
    #pragma unroll
    for (int i = 0; i < 16; i++) {
        int flat = i*256 + tid;
        int row = flat >> 5, c4 = flat & 31;
        *(float4*)&Ws[row*PITCH_A + c4*4] =
            *(const float4*)&g_W1[(size_t)(bn + row)*128 + c4*4];
    }
    __syncthreads();

    float acc[2][8][4];
    #pragma unroll
    for (int mf = 0; mf < 2; mf++)
        #pragma unroll
        for (int nf = 0; nf < 8; nf++)
            #pragma unroll
            for (int j = 0; j < 4; j++) acc[mf][nf][j] = 0.0f;

    #pragma unroll 4
    for (int ks = 0; ks < 16; ks++) {
        int k0 = ks*8;
        uint32_t a[2][4], b[8][2];
        #pragma unroll
        for (int mf = 0; mf < 2; mf++) {
            int r0 = wm*32 + mf*16 + g;
            a[mf][0] = __float_as_uint(As[r0*PITCH_A + k0 + t]);
            a[mf][1] = __float_as_uint(As[(r0+8)*PITCH_A + k0 + t]);
            a[mf][2] = __float_as_uint(As[r0*PITCH_A + k0 + t + 4]);
            a[mf][3] = __float_as_uint(As[(r0+8)*PITCH_A + k0 + t + 4]);
        }
        #pragma unroll
        for (int nf = 0; nf < 8; nf++) {
            int n0 = wn*64 + nf*8 + g;
            b[nf][0] = __float_as_uint(Ws[n0*PITCH_A + k0 + t]);
            b[nf][1] = __float_as_uint(Ws[n0*PITCH_A + k0 + t + 4]);
        }
        #pragma unroll
        for (int mf = 0; mf < 2; mf++)
            #pragma unroll
            for (int nf = 0; nf < 8; nf++)
                mma_tf32(acc[mf][nf], a[mf], b[nf]);
    }

    // store: c0,c1 at (row, 2t), c2,c3 at (row+8, 2t)
    float* buf = (float*)g_Bu;
    #pragma unroll
    for (int mf = 0; mf < 2; mf++) {
        int row = bm + wm*32 + mf*16 + g;
        #pragma unroll
        for (int nf = 0; nf < 8; nf++) {
            int col = bn + wn*64 + nf*8 + 2*t;
            *(float2*)&buf[(size_t)row*256 + col]     = make_float2(acc[mf][nf][0], acc[mf][nf][1]);
            *(float2*)&buf[(size_t)(row+8)*256 + col] = make_float2(acc[mf][nf][2], acc[mf][nf][3]);
        }
    }
}

// ---------------- GEMM2: out(M x 128) = ys(M x 256) @ W2^T + D*x --------------
#define PITCH_W2 260
__global__ void __launch_bounds__(256, 1)
gemm2_kernel(float* __restrict__ outp, const float* __restrict__ x,
             const float* __restrict__ Dv) {
    extern __shared__ float smem[];
    float* As = smem;                    // [128][132] (one K-half at a time)
    float* Ws = smem + 128*PITCH_A;      // [128][260] full K=256
    int tid = threadIdx.x;
    int wid = tid >> 5, lane = tid & 31;
    int wm = wid >> 1, wn = wid & 1;
    int g = lane >> 2, t = lane & 3;
    int bm = blockIdx.y * 128;
    const float* ysf = (const float*)g_ys;

    #pragma unroll
    for (int i = 0; i < 32; i++) {
        int flat = i*256 + tid;
        int row = flat >> 6, c4 = flat & 63;
        *(float4*)&Ws[row*PITCH_W2 + c4*4] =
            *(const float4*)&g_W2[(size_t)row*256 + c4*4];
    }

    float acc[2][8][4];
    #pragma unroll
    for (int mf = 0; mf < 2; mf++)
        #pragma unroll
        for (int nf = 0; nf < 8; nf++)
            #pragma unroll
            for (int j = 0; j < 4; j++) acc[mf][nf][j] = 0.0f;

    for (int r = 0; r < 2; r++) {
        __syncthreads();
        #pragma unroll
        for (int i = 0; i < 16; i++) {
            int flat = i*256 + tid;
            int row = flat >> 5, c4 = flat & 31;
            *(float4*)&As[row*PITCH_A + c4*4] =
                *(const float4*)&ysf[(size_t)(bm + row)*256 + r*128 + c4*4];
        }
        __syncthreads();
        #pragma unroll 4
        for (int ks = 0; ks < 16; ks++) {
            int k0 = ks*8;           // local col in As
            int kg = r*128 + k0;     // global col in Ws
            uint32_t a[2][4], b[8][2];
            #pragma unroll
            for (int mf = 0; mf < 2; mf++) {
                int r0 = wm*32 + mf*16 + g;
                a[mf][0] = __float_as_uint(As[r0*PITCH_A + k0 + t]);
                a[mf][1] = __float_as_uint(As[(r0+8)*PITCH_A + k0 + t]);
                a[mf][2] = __float_as_uint(As[r0*PITCH_A + k0 + t + 4]);
                a[mf][3] = __float_as_uint(As[(r0+8)*PITCH_A + k0 + t + 4]);
            }
            #pragma unroll
            for (int nf = 0; nf < 8; nf++) {
                int n0 = wn*64 + nf*8 + g;
                b[nf][0] = __float_as_uint(Ws[n0*PITCH_W2 + kg + t]);
                b[nf][1] = __float_as_uint(Ws[n0*PITCH_W2 + kg + t + 4]);
            }
            #pragma unroll
            for (int mf = 0; mf < 2; mf++)
                #pragma unroll
                for (int nf = 0; nf < 8; nf++)
                    mma_tf32(acc[mf][nf], a[mf], b[nf]);
        }
    }

    #pragma unroll
    for (int mf = 0; mf < 2; mf++) {
        int row = bm + wm*32 + mf*16 + g;
        #pragma unroll
        for (int nf = 0; nf < 8; nf++) {
            int col = wn*64 + nf*8 + 2*t;
            float2 d0 = *(const float2*)&Dv[col];
            float2 x0 = *(const float2*)&x[(size_t)row*128 + col];
            float2 x1 = *(const float2*)&x[(size_t)(row+8)*128 + col];
            float2 o0 = make_float2(acc[mf][nf][0] + d0.x*x0.x, acc[mf][nf][1] + d0.y*x0.y);
            float2 o1 = make_float2(acc[mf][nf][2] + d0.x*x1.x, acc[mf][nf][3] + d0.y*x1.y);
            *(float2*)&outp[(size_t)row*128 + col]     = o0;
            *(float2*)&outp[(size_t)(row+8)*128 + col] = o1;
        }
    }
}

// ---------------- scan pass 1: per-chunk partial sums -------------------------
__global__ void scan_partial_kernel() {
    int p = threadIdx.x;
    int c = blockIdx.x;
    int b = blockIdx.y;
    float4 Mv = g_M[p];
    float2 cv = g_c[p];
    float h1r = 0.f, h1i = 0.f, h2r = 0.f, h2i = 0.f;
    size_t base = ((size_t)b*LEN_ + (size_t)c*CH) * PDIM + p;
    #pragma unroll 8
    for (int l = 0; l < CH; l++) {
        float2 bu = g_Bu[base + (size_t)l*PDIM];
        float n1r = Mv.x*h1r + Mv.y*h2r + cv.x*bu.x;
        float n1i = Mv.x*h1i + Mv.y*h2i + cv.x*bu.y;
        float n2r = Mv.z*h1r + Mv.w*h2r + cv.y*bu.x;
        float n2i = Mv.z*h1i + Mv.w*h2i + cv.y*bu.y;
        h1r = n1r; h1i = n1i; h2r = n2r; h2i = n2i;
    }
    g_csum[(b*NC + c)*PDIM + p] = make_float4(h1r, h1i, h2r, h2i);
}

// ---------------- scan pass 2: carry combine (batched prefetch, MLP=8) --------
__global__ void scan_carry_kernel() {
    int p = threadIdx.x;
    int b = blockIdx.x;
    float4 Mp = g_Mp[p];
    float h1r = 0.f, h1i = 0.f, h2r = 0.f, h2i = 0.f;
    for (int c0 = 0; c0 < NC; c0 += 8) {
        float4 s[8];
        #pragma unroll
        for (int j = 0; j < 8; j++)
            s[j] = g_csum[(b*NC + c0 + j)*PDIM + p];
        #pragma unroll
        for (int j = 0; j < 8; j++) {
            g_cin[(b*NC + c0 + j)*PDIM + p] = make_float4(h1r, h1i, h2r, h2i);
            float n1r = Mp.x*h1r + Mp.y*h2r + s[j].x;
            float n1i = Mp.x*h1i + Mp.y*h2i + s[j].y;
            float n2r = Mp.z*h1r + Mp.w*h2r + s[j].z;
            float n2i = Mp.z*h1i + Mp.w*h2i + s[j].w;
            h1r = n1r; h1i = n1i; h2r = n2r; h2i = n2i;
        }
    }
}

// ---------------- scan pass 3: final scan, writes ys (tf32-rounded) -----------
__global__ void scan_final_kernel() {
    int p = threadIdx.x;
    int c = blockIdx.x;
    int b = blockIdx.y;
    float4 Mv = g_M[p];
    float2 cv = g_c[p];
    float4 hin = g_cin[(b*NC + c)*PDIM + p];
    float h1r = hin.x, h1i = hin.y, h2r = hin.z, h2i = hin.w;
    size_t base = ((size_t)b*LEN_ + (size_t)c*CH) * PDIM + p;
    #pragma unroll 8
    for (int l = 0; l < CH; l++) {
        float2 bu = g_Bu[base + (size_t)l*PDIM];
        float n1r = Mv.x*h1r + Mv.y*h2r + cv.x*bu.x;
        float n1i = Mv.x*h1i + Mv.y*h2i + cv.x*bu.y;
        float n2r = Mv.z*h1r + Mv.w*h2r + cv.y*bu.x;
        float n2i = Mv.z*h1i + Mv.w*h2i + cv.y*bu.y;
        h1r = n1r; h1i = n1i; h2r = n2r; h2i = n2i;
        g_ys[base + (size_t)l*PDIM] = make_float2(tf32r(h2r), tf32r(h2i));
    }
}

// ---------------- launch ------------------------------------------------------
extern "C" void kernel_launch(void* const* d_in, const int* in_sizes, int n_in,
                              void* d_out, int out_size) {
    const float* x  = (const float*)d_in[0];
    const float* Ad = (const float*)d_in[1];
    const float* Gd = (const float*)d_in[2];
    const float* dt = (const float*)d_in[3];
    const float* B  = (const float*)d_in[4];
    const float* C  = (const float*)d_in[5];
    const float* D  = (const float*)d_in[6];
    float* out = (float*)d_out;

    const int SMEM1 = 2 * 128 * PITCH_A * 4;                    // 135168
    const int SMEM2 = 128 * PITCH_A * 4 + 128 * PITCH_W2 * 4;   // 200704
    cudaFuncSetAttribute(gemm1_kernel, cudaFuncAttributeMaxDynamicSharedMemorySize, SMEM1);
    cudaFuncSetAttribute(gemm2_kernel, cudaFuncAttributeMaxDynamicSharedMemorySize, SMEM2);

    const int M = BSZ_ * LEN_;   // 65536

    prep_kernel<<<1, 256>>>(Ad, Gd, dt, B, C);
    gemm1_kernel<<<dim3(2, M/128), 256, SMEM1>>>(x);
    scan_partial_kernel<<<dim3(NC, BSZ_), PDIM>>>();
    scan_carry_kernel<<<BSZ_, PDIM>>>();
    scan_final_kernel<<<dim3(NC, BSZ_), PDIM>>>();
    gemm2_kernel<<<dim3(1, M/128), 256, SMEM2>>>(out, x, D);
}

// round 5
// speedup vs baseline: 2.0210x; 1.1636x over previous
#include <cuda_runtime.h>
#include <cuda_fp16.h>
#include <math.h>
#include <stdint.h>

#define BSZ_ 8
#define LEN_ 8192
#define PDIM 128
#define HDIM 128
#define CH 128
#define NC (LEN_/CH)          // 64
#define MROWS (BSZ_*LEN_)     // 65536
#define PA 136                // smem pitch in halfs (272B = 68 words ≡ 4 mod 32)

// ---------------- scratch ----------------------------------------------------
__device__ float2 g_Bu[(size_t)MROWS*PDIM];        // 64 MB (b,l,p) complex fp32
__device__ __half g_ysh[(size_t)MROWS*2*PDIM];     // 32 MB ys as half (row, 2p+ri)
__device__ float4 g_csum[BSZ_*NC*PDIM];
__device__ float4 g_cin [BSZ_*NC*PDIM];
__device__ float4 g_M  [PDIM];
__device__ float2 g_c  [PDIM];
__device__ float4 g_Mp [PDIM];                     // M^CH
__device__ __half g_W1t[HDIM*2*PDIM];              // [k=h][n=2p+ri]
__device__ __half g_W2t[2*PDIM*HDIM];              // [k=2p+ri][n=h] (sign folded)

// ---------------- helpers ----------------------------------------------------
__device__ __forceinline__ uint32_t smem_u32(const void* p) {
    uint32_t a;
    asm("{ .reg .u64 t; cvta.to.shared.u64 t, %1; cvt.u32.u64 %0, t; }" : "=r"(a) : "l"(p));
    return a;
}
__device__ __forceinline__ void ldsm4(uint32_t addr, uint32_t* r) {
    asm volatile("ldmatrix.sync.aligned.m8n8.x4.shared.b16 {%0,%1,%2,%3}, [%4];"
                 : "=r"(r[0]), "=r"(r[1]), "=r"(r[2]), "=r"(r[3]) : "r"(addr));
}
__device__ __forceinline__ void ldsm4t(uint32_t addr, uint32_t* r) {
    asm volatile("ldmatrix.sync.aligned.m8n8.x4.trans.shared.b16 {%0,%1,%2,%3}, [%4];"
                 : "=r"(r[0]), "=r"(r[1]), "=r"(r[2]), "=r"(r[3]) : "r"(addr));
}
__device__ __forceinline__ void mma_f16(float* d, const uint32_t* a, const uint32_t* b) {
    asm volatile(
        "mma.sync.aligned.m16n8k16.row.col.f32.f16.f16.f32 "
        "{%0,%1,%2,%3}, {%4,%5,%6,%7}, {%8,%9}, {%0,%1,%2,%3};"
        : "+f"(d[0]), "+f"(d[1]), "+f"(d[2]), "+f"(d[3])
        : "r"(a[0]), "r"(a[1]), "r"(a[2]), "r"(a[3]), "r"(b[0]), "r"(b[1]));
}

// ---------------- prep -------------------------------------------------------
__global__ void prep_kernel(const float* __restrict__ Ad, const float* __restrict__ Gd,
                            const float* __restrict__ dtv,
                            const float* __restrict__ Bin, const float* __restrict__ Cin) {
    int tid = threadIdx.x;
    if (tid < PDIM) {
        int p = tid;
        float dts = 1.0f / (1.0f + expf(-dtv[p]));
        float A   = fmaxf(Ad[p], 0.0f);
        float G   = fmaxf(Gd[p], 0.0f);
        float dt2 = fmaxf(dts*dts, 1e-6f);
        float s   = sqrtf(1.0f + dts*G);
        float alo = (2.0f + dts*G - 2.0f*s) / dt2;
        float ahi = (2.0f + dts*G + 2.0f*s) / dt2;
        float Af  = fminf(fmaxf(A, alo), ahi);
        float S    = 1.0f + dts*G;
        float invS = 1.0f / S;
        float m11 = invS;
        float m12 = -dts*invS*Af;
        float m21 = dts*invS;
        float m22 = 1.0f - dts*dts*invS*Af;
        g_M[p] = make_float4(m11, m12, m21, m22);
        g_c[p] = make_float2(dts*invS, dts*dts*invS);
        float a = m11, b = m12, c = m21, d = m22;
        #pragma unroll
        for (int i = 0; i < 7; i++) {   // M^128
            float na = a*a + b*c;
            float nb = a*b + b*d;
            float nc = c*a + d*c;
            float nd = c*b + d*d;
            a = na; b = nb; c = nc; d = nd;
        }
        g_Mp[p] = make_float4(a, b, c, d);
    }
    // W1t[k=h][n=2p+ri] = B[p][h][ri]  (B layout (P,H,2))
    for (int idx = tid; idx < HDIM*2*PDIM; idx += blockDim.x) {
        int h = idx / (2*PDIM), n = idx % (2*PDIM);
        int p = n >> 1, ri = n & 1;
        g_W1t[idx] = __float2half(Bin[((size_t)p*HDIM + h)*2 + ri]);
    }
    // W2t[k=2p+ri][n=h] = +-C[h][p][ri]  (C flat = [h][2p+ri])
    for (int idx = tid; idx < 2*PDIM*HDIM; idx += blockDim.x) {
        int k = idx / HDIM, h = idx % HDIM;
        float v = Cin[(size_t)h*2*PDIM + k];
        g_W2t[idx] = __float2half((k & 1) ? -v : v);
    }
}

// ---------------- GEMM1 (+fused chunk-partial scan) ---------------------------
// Bu(M x 256) = x(M x 128) @ W1^T, fp16 mma m16n8k16, 8 warps (4x2)
__global__ void __launch_bounds__(256, 2)
gemm1_kernel(const float* __restrict__ x) {
    extern __shared__ __align__(16) char smem[];
    __half* Ah = (__half*)smem;                    // [128][PA]
    __half* Bh = (__half*)(smem + 128*PA*2);       // [128][PA]
    float*  stage = (float*)smem;                  // alias, [128][130]
    uint32_t sA = smem_u32(Ah), sB = smem_u32(Bh);
    int tid = threadIdx.x, lane = tid & 31, wid = tid >> 5;
    int wm = wid >> 1, wn = wid & 1;
    int g = lane >> 2, t = lane & 3;
    int bm = blockIdx.y * 128, bn = blockIdx.x * 128;
    uint32_t arow = (uint32_t)(lane & 15);
    uint32_t asel = (uint32_t)((lane >> 4) * 8);

    // load x tile -> half
    #pragma unroll
    for (int i = 0; i < 16; i++) {
        int flat = i*256 + tid;
        int row = flat >> 5, c4 = flat & 31;
        float4 v = *(const float4*)&x[(size_t)(bm + row)*128 + c4*4];
        *(__half2*)&Ah[row*PA + c4*4]     = __floats2half2_rn(v.x, v.y);
        *(__half2*)&Ah[row*PA + c4*4 + 2] = __floats2half2_rn(v.z, v.w);
    }
    // load W1t (k=0..127, cols bn..bn+127)
    #pragma unroll
    for (int i = 0; i < 8; i++) {
        int flat = i*256 + tid;
        int k = flat >> 4, ch = flat & 15;
        *(uint4*)&Bh[k*PA + ch*8] = *(const uint4*)&g_W1t[(size_t)k*2*PDIM + bn + ch*8];
    }
    __syncthreads();

    float acc[2][8][4] = {};
    #pragma unroll
    for (int ks = 0; ks < 8; ks++) {
        int k0 = ks*16;
        uint32_t a[2][4], b[8][2];
        #pragma unroll
        for (int mf = 0; mf < 2; mf++)
            ldsm4(sA + ((wm*32 + mf*16 + arow)*PA + k0 + asel)*2, a[mf]);
        #pragma unroll
        for (int np = 0; np < 4; np++) {
            uint32_t r[4];
            ldsm4t(sB + ((k0 + arow)*PA + wn*64 + np*16 + asel)*2, r);
            b[np*2][0] = r[0]; b[np*2][1] = r[1];
            b[np*2+1][0] = r[2]; b[np*2+1][1] = r[3];
        }
        #pragma unroll
        for (int mf = 0; mf < 2; mf++)
            #pragma unroll
            for (int nf = 0; nf < 8; nf++)
                mma_f16(acc[mf][nf], a[mf], b[nf]);
    }

    // write Bu (fp32) to global
    float* bubuf = (float*)g_Bu;
    #pragma unroll
    for (int mf = 0; mf < 2; mf++) {
        int row = bm + wm*32 + mf*16 + g;
        #pragma unroll
        for (int nf = 0; nf < 8; nf++) {
            int col = bn + wn*64 + nf*8 + 2*t;
            *(float2*)&bubuf[(size_t)row*256 + col]     = make_float2(acc[mf][nf][0], acc[mf][nf][1]);
            *(float2*)&bubuf[(size_t)(row+8)*256 + col] = make_float2(acc[mf][nf][2], acc[mf][nf][3]);
        }
    }

    // fused chunk-partial scan: stage acc in smem (A/B tiles are dead)
    __syncthreads();
    #pragma unroll
    for (int mf = 0; mf < 2; mf++) {
        int rl = wm*32 + mf*16 + g;
        #pragma unroll
        for (int nf = 0; nf < 8; nf++) {
            int cl = wn*64 + nf*8 + 2*t;
            *(float2*)&stage[rl*130 + cl]     = make_float2(acc[mf][nf][0], acc[mf][nf][1]);
            *(float2*)&stage[(rl+8)*130 + cl] = make_float2(acc[mf][nf][2], acc[mf][nf][3]);
        }
    }
    __syncthreads();
    if (tid < 64) {
        int pg = (bn >> 1) + tid;      // global p handled by this CTA
        float4 Mv = g_M[pg];
        float2 cv = g_c[pg];
        float h1r = 0.f, h1i = 0.f, h2r = 0.f, h2i = 0.f;
        #pragma unroll 8
        for (int l = 0; l < CH; l++) {
            float2 bu = *(float2*)&stage[l*130 + 2*tid];
            float n1r = Mv.x*h1r + Mv.y*h2r + cv.x*bu.x;
            float n1i = Mv.x*h1i + Mv.y*h2i + cv.x*bu.y;
            float n2r = Mv.z*h1r + Mv.w*h2r + cv.y*bu.x;
            float n2i = Mv.z*h1i + Mv.w*h2i + cv.y*bu.y;
            h1r = n1r; h1i = n1i; h2r = n2r; h2i = n2i;
        }
        int b = blockIdx.y >> 6;       // 64 row-blocks per batch
        int c = blockIdx.y & 63;
        g_csum[(b*NC + c)*PDIM + pg] = make_float4(h1r, h1i, h2r, h2i);
    }
}

// ---------------- carry: scan over chunks with M^CH (batch 16) ----------------
__global__ void scan_carry_kernel() {
    int p = threadIdx.x;
    int b = blockIdx.x;
    float4 Mp = g_Mp[p];
    float h1r = 0.f, h1i = 0.f, h2r = 0.f, h2i = 0.f;
    for (int c0 = 0; c0 < NC; c0 += 16) {
        float4 s[16];
        #pragma unroll
        for (int j = 0; j < 16; j++)
            s[j] = g_csum[(b*NC + c0 + j)*PDIM + p];
        #pragma unroll
        for (int j = 0; j < 16; j++) {
            g_cin[(b*NC + c0 + j)*PDIM + p] = make_float4(h1r, h1i, h2r, h2i);
            float n1r = Mp.x*h1r + Mp.y*h2r + s[j].x;
            float n1i = Mp.x*h1i + Mp.y*h2i + s[j].y;
            float n2r = Mp.z*h1r + Mp.w*h2r + s[j].z;
            float n2i = Mp.z*h1i + Mp.w*h2i + s[j].w;
            h1r = n1r; h1i = n1i; h2r = n2r; h2i = n2i;
        }
    }
}

// ---------------- pass3: final scan, writes ys as half2 -----------------------
__global__ void scan_final_kernel() {
    int p = threadIdx.x;
    int c = blockIdx.x;
    int b = blockIdx.y;
    float4 Mv = g_M[p];
    float2 cv = g_c[p];
    float4 hin = g_cin[(b*NC + c)*PDIM + p];
    float h1r = hin.x, h1i = hin.y, h2r = hin.z, h2i = hin.w;
    size_t base = ((size_t)b*LEN_ + (size_t)c*CH) * PDIM + p;
    #pragma unroll 8
    for (int l = 0; l < CH; l++) {
        float2 bu = g_Bu[base + (size_t)l*PDIM];
        float n1r = Mv.x*h1r + Mv.y*h2r + cv.x*bu.x;
        float n1i = Mv.x*h1i + Mv.y*h2i + cv.x*bu.y;
        float n2r = Mv.z*h1r + Mv.w*h2r + cv.y*bu.x;
        float n2i = Mv.z*h1i + Mv.w*h2i + cv.y*bu.y;
        h1r = n1r; h1i = n1i; h2r = n2r; h2i = n2i;
        *(__half2*)&g_ysh[(base + (size_t)l*PDIM)*2] = __floats2half2_rn(h2r, h2i);
    }
}

// ---------------- GEMM2: out(M x 128) = ys(M x 256) @ W2^T + D*x --------------
__global__ void __launch_bounds__(256, 2)
gemm2_kernel(float* __restrict__ outp, const float* __restrict__ x,
             const float* __restrict__ Dv) {
    extern __shared__ __align__(16) char smem[];
    __half* Ah = (__half*)smem;                    // [128][PA] (one K-half)
    __half* Bh = (__half*)(smem + 128*PA*2);       // [128][PA]
    uint32_t sA = smem_u32(Ah), sB = smem_u32(Bh);
    int tid = threadIdx.x, lane = tid & 31, wid = tid >> 5;
    int wm = wid >> 1, wn = wid & 1;
    int g = lane >> 2, t = lane & 3;
    int bm = blockIdx.x * 128;
    uint32_t arow = (uint32_t)(lane & 15);
    uint32_t asel = (uint32_t)((lane >> 4) * 8);

    float acc[2][8][4] = {};
    for (int r = 0; r < 2; r++) {
        if (r) __syncthreads();
        #pragma unroll
        for (int i = 0; i < 8; i++) {
            int flat = i*256 + tid;
            int row = flat >> 4, ch = flat & 15;
            *(uint4*)&Ah[row*PA + ch*8] =
                *(const uint4*)&g_ysh[(size_t)(bm + row)*2*PDIM + r*128 + ch*8];
        }
        #pragma unroll
        for (int i = 0; i < 8; i++) {
            int flat = i*256 + tid;
            int k = flat >> 4, ch = flat & 15;
            *(uint4*)&Bh[k*PA + ch*8] =
                *(const uint4*)&g_W2t[(size_t)(r*128 + k)*HDIM + ch*8];
        }
        __syncthreads();
        #pragma unroll
        for (int ks = 0; ks < 8; ks++) {
            int k0 = ks*16;
            uint32_t a[2][4], b[8][2];
            #pragma unroll
            for (int mf = 0; mf < 2; mf++)
                ldsm4(sA + ((wm*32 + mf*16 + arow)*PA + k0 + asel)*2, a[mf]);
            #pragma unroll
            for (int np = 0; np < 4; np++) {
                uint32_t rr[4];
                ldsm4t(sB + ((k0 + arow)*PA + wn*64 + np*16 + asel)*2, rr);
                b[np*2][0] = rr[0]; b[np*2][1] = rr[1];
                b[np*2+1][0] = rr[2]; b[np*2+1][1] = rr[3];
            }
            #pragma unroll
            for (int mf = 0; mf < 2; mf++)
                #pragma unroll
                for (int nf = 0; nf < 8; nf++)
                    mma_f16(acc[mf][nf], a[mf], b[nf]);
        }
    }

    #pragma unroll
    for (int mf = 0; mf < 2; mf++) {
        int row = bm + wm*32 + mf*16 + g;
        #pragma unroll
        for (int nf = 0; nf < 8; nf++) {
            int col = wn*64 + nf*8 + 2*t;
            float2 d0 = *(const float2*)&Dv[col];
            float2 x0 = *(const float2*)&x[(size_t)row*128 + col];
            float2 x1 = *(const float2*)&x[(size_t)(row+8)*128 + col];
            float2 o0 = make_float2(acc[mf][nf][0] + d0.x*x0.x, acc[mf][nf][1] + d0.y*x0.y);
            float2 o1 = make_float2(acc[mf][nf][2] + d0.x*x1.x, acc[mf][nf][3] + d0.y*x1.y);
            *(float2*)&outp[(size_t)row*128 + col]     = o0;
            *(float2*)&outp[(size_t)(row+8)*128 + col] = o1;
        }
    }
}

// ---------------- launch ------------------------------------------------------
extern "C" void kernel_launch(void* const* d_in, const int* in_sizes, int n_in,
                              void* d_out, int out_size) {
    const float* x  = (const float*)d_in[0];
    const float* Ad = (const float*)d_in[1];
    const float* Gd = (const float*)d_in[2];
    const float* dt = (const float*)d_in[3];
    const float* B  = (const float*)d_in[4];
    const float* C  = (const float*)d_in[5];
    const float* D  = (const float*)d_in[6];
    float* out = (float*)d_out;

    const int SMEM = 2 * 128 * PA * 2;   // 69632 bytes
    cudaFuncSetAttribute(gemm1_kernel, cudaFuncAttributeMaxDynamicSharedMemorySize, SMEM);
    cudaFuncSetAttribute(gemm2_kernel, cudaFuncAttributeMaxDynamicSharedMemorySize, SMEM);

    prep_kernel<<<1, 256>>>(Ad, Gd, dt, B, C);
    gemm1_kernel<<<dim3(2, MROWS/128), 256, SMEM>>>(x);
    scan_carry_kernel<<<BSZ_, 128>>>();
    scan_final_kernel<<<dim3(NC, BSZ_), 128>>>();
    gemm2_kernel<<<MROWS/128, 256, SMEM>>>(out, x, D);
}

// round 8
// speedup vs baseline: 2.9808x; 1.4750x over previous
#include <cuda_runtime.h>
#include <cuda_fp16.h>
#include <math.h>
#include <stdint.h>

#define BSZ_ 8
#define LEN_ 8192
#define PDIM 128
#define HDIM 128
#define CH 128
#define NC (LEN_/CH)          // 64
#define MROWS (BSZ_*LEN_)     // 65536
#define PA 136                // smem pitch (halfs) for K=128 tiles
#define PY 264                // smem pitch (halfs) for K=256 ys tile
#define PB 136                // smem pitch (halfs) for W2 tile

// ---------------- scratch ----------------------------------------------------
__device__ __half2 g_Buh[(size_t)MROWS*PDIM];      // 32 MB Bu as half2 (row, p)
__device__ float4 g_csum[BSZ_*NC*PDIM];
__device__ float4 g_cin [BSZ_*NC*PDIM];
__device__ float4 g_M  [PDIM];
__device__ float2 g_c  [PDIM];
__device__ float4 g_Mp [PDIM];                     // M^CH
__device__ __half g_W1t[HDIM*2*PDIM];              // [k=h][n=2p+ri]
__device__ __half g_W2t[2*PDIM*HDIM];              // [k=2p+ri][n=h] (sign folded)

// ---------------- helpers ----------------------------------------------------
__device__ __forceinline__ uint32_t smem_u32(const void* p) {
    uint32_t a;
    asm("{ .reg .u64 t; cvta.to.shared.u64 t, %1; cvt.u32.u64 %0, t; }" : "=r"(a) : "l"(p));
    return a;
}
__device__ __forceinline__ void ldsm4(uint32_t addr, uint32_t* r) {
    asm volatile("ldmatrix.sync.aligned.m8n8.x4.shared.b16 {%0,%1,%2,%3}, [%4];"
                 : "=r"(r[0]), "=r"(r[1]), "=r"(r[2]), "=r"(r[3]) : "r"(addr));
}
__device__ __forceinline__ void ldsm4t(uint32_t addr, uint32_t* r) {
    asm volatile("ldmatrix.sync.aligned.m8n8.x4.trans.shared.b16 {%0,%1,%2,%3}, [%4];"
                 : "=r"(r[0]), "=r"(r[1]), "=r"(r[2]), "=r"(r[3]) : "r"(addr));
}
__device__ __forceinline__ void mma_f16(float* d, const uint32_t* a, const uint32_t* b) {
    asm volatile(
        "mma.sync.aligned.m16n8k16.row.col.f32.f16.f16.f32 "
        "{%0,%1,%2,%3}, {%4,%5,%6,%7}, {%8,%9}, {%0,%1,%2,%3};"
        : "+f"(d[0]), "+f"(d[1]), "+f"(d[2]), "+f"(d[3])
        : "r"(a[0]), "r"(a[1]), "r"(a[2]), "r"(a[3]), "r"(b[0]), "r"(b[1]));
}

// ---------------- prep -------------------------------------------------------
__global__ void prep_kernel(const float* __restrict__ Ad, const float* __restrict__ Gd,
                            const float* __restrict__ dtv,
                            const float* __restrict__ Bin, const float* __restrict__ Cin) {
    int tid = threadIdx.x;
    if (tid < PDIM) {
        int p = tid;
        float dts = 1.0f / (1.0f + expf(-dtv[p]));
        float A   = fmaxf(Ad[p], 0.0f);
        float G   = fmaxf(Gd[p], 0.0f);
        float dt2 = fmaxf(dts*dts, 1e-6f);
        float s   = sqrtf(1.0f + dts*G);
        float alo = (2.0f + dts*G - 2.0f*s) / dt2;
        float ahi = (2.0f + dts*G + 2.0f*s) / dt2;
        float Af  = fminf(fmaxf(A, alo), ahi);
        float S    = 1.0f + dts*G;
        float invS = 1.0f / S;
        float m11 = invS;
        float m12 = -dts*invS*Af;
        float m21 = dts*invS;
        float m22 = 1.0f - dts*dts*invS*Af;
        g_M[p] = make_float4(m11, m12, m21, m22);
        g_c[p] = make_float2(dts*invS, dts*dts*invS);
        float a = m11, b = m12, c = m21, d = m22;
        #pragma unroll
        for (int i = 0; i < 7; i++) {   // M^128
            float na = a*a + b*c;
            float nb = a*b + b*d;
            float nc = c*a + d*c;
            float nd = c*b + d*d;
            a = na; b = nb; c = nc; d = nd;
        }
        g_Mp[p] = make_float4(a, b, c, d);
    }
    for (int idx = tid; idx < HDIM*2*PDIM; idx += blockDim.x) {
        int h = idx / (2*PDIM), n = idx % (2*PDIM);
        int p = n >> 1, ri = n & 1;
        g_W1t[idx] = __float2half(Bin[((size_t)p*HDIM + h)*2 + ri]);
    }
    for (int idx = tid; idx < 2*PDIM*HDIM; idx += blockDim.x) {
        int k = idx / HDIM, h = idx % HDIM;
        float v = Cin[(size_t)h*2*PDIM + k];
        g_W2t[idx] = __float2half((k & 1) ? -v : v);
    }
}

// ---------------- GEMM1 (+fused chunk-partial scan), writes Bu as half --------
__global__ void __launch_bounds__(256, 2)
gemm1_kernel(const float* __restrict__ x) {
    extern __shared__ __align__(16) char smem[];
    __half* Ah = (__half*)smem;                    // [128][PA]
    __half* Bh = (__half*)(smem + 128*PA*2);       // [128][PA]
    float*  stage = (float*)smem;                  // alias, [128][130]
    uint32_t sA = smem_u32(Ah), sB = smem_u32(Bh);
    int tid = threadIdx.x, lane = tid & 31, wid = tid >> 5;
    int wm = wid >> 1, wn = wid & 1;
    int g = lane >> 2, t = lane & 3;
    int bm = blockIdx.y * 128, bn = blockIdx.x * 128;
    uint32_t arow = (uint32_t)(lane & 15);
    uint32_t asel = (uint32_t)((lane >> 4) * 8);

    #pragma unroll
    for (int i = 0; i < 16; i++) {
        int flat = i*256 + tid;
        int row = flat >> 5, c4 = flat & 31;
        float4 v = *(const float4*)&x[(size_t)(bm + row)*128 + c4*4];
        *(__half2*)&Ah[row*PA + c4*4]     = __floats2half2_rn(v.x, v.y);
        *(__half2*)&Ah[row*PA + c4*4 + 2] = __floats2half2_rn(v.z, v.w);
    }
    #pragma unroll
    for (int i = 0; i < 8; i++) {
        int flat = i*256 + tid;
        int k = flat >> 4, ch = flat & 15;
        *(uint4*)&Bh[k*PA + ch*8] = *(const uint4*)&g_W1t[(size_t)k*2*PDIM + bn + ch*8];
    }
    __syncthreads();

    float acc[2][8][4] = {};
    #pragma unroll
    for (int ks = 0; ks < 8; ks++) {
        int k0 = ks*16;
        uint32_t a[2][4], b[8][2];
        #pragma unroll
        for (int mf = 0; mf < 2; mf++)
            ldsm4(sA + ((wm*32 + mf*16 + arow)*PA + k0 + asel)*2, a[mf]);
        #pragma unroll
        for (int np = 0; np < 4; np++) {
            uint32_t r[4];
            ldsm4t(sB + ((k0 + arow)*PA + wn*64 + np*16 + asel)*2, r);
            b[np*2][0] = r[0]; b[np*2][1] = r[1];
            b[np*2+1][0] = r[2]; b[np*2+1][1] = r[3];
        }
        #pragma unroll
        for (int mf = 0; mf < 2; mf++)
            #pragma unroll
            for (int nf = 0; nf < 8; nf++)
                mma_f16(acc[mf][nf], a[mf], b[nf]);
    }

    // stage acc to smem (A/B tiles dead)
    __syncthreads();
    #pragma unroll
    for (int mf = 0; mf < 2; mf++) {
        int rl = wm*32 + mf*16 + g;
        #pragma unroll
        for (int nf = 0; nf < 8; nf++) {
            int cl = wn*64 + nf*8 + 2*t;
            *(float2*)&stage[rl*130 + cl]     = make_float2(acc[mf][nf][0], acc[mf][nf][1]);
            *(float2*)&stage[(rl+8)*130 + cl] = make_float2(acc[mf][nf][2], acc[mf][nf][3]);
        }
    }
    __syncthreads();

    // coalesced half2 write of Bu (this CTA covers p in [bn/2, bn/2+64))
    int pbase = bn >> 1;
    #pragma unroll
    for (int i = 0; i < 32; i++) {
        int flat = i*256 + tid;
        int row = flat >> 6, j = flat & 63;
        float2 v = *(float2*)&stage[row*130 + 2*j];
        g_Buh[(size_t)(bm + row)*PDIM + pbase + j] = __floats2half2_rn(v.x, v.y);
    }

    // fused chunk-partial scan (64 p per CTA)
    if (tid < 64) {
        int pg = pbase + tid;
        float4 Mv = g_M[pg];
        float2 cv = g_c[pg];
        float h1r = 0.f, h1i = 0.f, h2r = 0.f, h2i = 0.f;
        #pragma unroll 8
        for (int l = 0; l < CH; l++) {
            float2 bu = *(float2*)&stage[l*130 + 2*tid];
            float n1r = Mv.x*h1r + Mv.y*h2r + cv.x*bu.x;
            float n1i = Mv.x*h1i + Mv.y*h2i + cv.x*bu.y;
            float n2r = Mv.z*h1r + Mv.w*h2r + cv.y*bu.x;
            float n2i = Mv.z*h1i + Mv.w*h2i + cv.y*bu.y;
            h1r = n1r; h1i = n1i; h2r = n2r; h2i = n2i;
        }
        int b = blockIdx.y >> 6;
        int c = blockIdx.y & 63;
        g_csum[(b*NC + c)*PDIM + pg] = make_float4(h1r, h1i, h2r, h2i);
    }
}

// ---------------- carry: scan over chunks with M^CH (batch 16) ----------------
__global__ void scan_carry_kernel() {
    int p = threadIdx.x;
    int b = blockIdx.x;
    float4 Mp = g_Mp[p];
    float h1r = 0.f, h1i = 0.f, h2r = 0.f, h2i = 0.f;
    for (int c0 = 0; c0 < NC; c0 += 16) {
        float4 s[16];
        #pragma unroll
        for (int j = 0; j < 16; j++)
            s[j] = g_csum[(b*NC + c0 + j)*PDIM + p];
        #pragma unroll
        for (int j = 0; j < 16; j++) {
            g_cin[(b*NC + c0 + j)*PDIM + p] = make_float4(h1r, h1i, h2r, h2i);
            float n1r = Mp.x*h1r + Mp.y*h2r + s[j].x;
            float n1i = Mp.x*h1i + Mp.y*h2i + s[j].y;
            float n2r = Mp.z*h1r + Mp.w*h2r + s[j].z;
            float n2i = Mp.z*h1i + Mp.w*h2i + s[j].w;
            h1r = n1r; h1i = n1i; h2r = n2r; h2i = n2i;
        }
    }
}

// ---------------- fused final: scan chunk in SMEM + GEMM2 + D*x ---------------
// SMEM: BuS [128][128] half2 (64K) | Ys [128][PY] half (67.6K) | W2 [256][PB] half (69.6K)
__global__ void __launch_bounds__(256, 1)
fused_final_kernel(float* __restrict__ outp, const float* __restrict__ x,
                   const float* __restrict__ Dv) {
    extern __shared__ __align__(16) char smem[];
    __half2* BuS = (__half2*)smem;                       // 65536 B
    __half*  Ys  = (__half*)(smem + 65536);              // 67584 B
    __half*  Wh  = (__half*)(smem + 65536 + 67584);      // 69632 B
    uint32_t sY = smem_u32(Ys), sW = smem_u32(Wh);
    int tid = threadIdx.x, lane = tid & 31, wid = tid >> 5;
    int wm = wid >> 1, wn = wid & 1;
    int g = lane >> 2, t = lane & 3;
    int c = blockIdx.x, b = blockIdx.y;
    int bm = (b*NC + c) * CH;                            // global row base
    uint32_t arow = (uint32_t)(lane & 15);
    uint32_t asel = (uint32_t)((lane >> 4) * 8);

    // incoming state for this chunk (threads 0-127, one per p)
    float4 hin;
    if (tid < 128) hin = g_cin[(b*NC + c)*PDIM + tid];

    // load Bu chunk: 64 KB flat copy
    const uint4* src = (const uint4*)&g_Buh[(size_t)bm*PDIM];
    uint4* dst = (uint4*)BuS;
    #pragma unroll
    for (int i = 0; i < 16; i++)
        dst[i*256 + tid] = src[i*256 + tid];
    __syncthreads();

    if (tid < 128) {
        // serial scan from SMEM, write ys (half) into ldmatrix-ready tile
        int p = tid;
        float4 Mv = g_M[p];
        float2 cv = g_c[p];
        float h1r = hin.x, h1i = hin.y, h2r = hin.z, h2i = hin.w;
        #pragma unroll 8
        for (int l = 0; l < CH; l++) {
            float2 bu = __half22float2(BuS[l*128 + p]);
            float n1r = Mv.x*h1r + Mv.y*h2r + cv.x*bu.x;
            float n1i = Mv.x*h1i + Mv.y*h2i + cv.x*bu.y;
            float n2r = Mv.z*h1r + Mv.w*h2r + cv.y*bu.x;
            float n2i = Mv.z*h1i + Mv.w*h2i + cv.y*bu.y;
            h1r = n1r; h1i = n1i; h2r = n2r; h2i = n2i;
            *(__half2*)&Ys[l*PY + 2*p] = __floats2half2_rn(h2r, h2i);
        }
    } else {
        // warps 4-7: load W2 (256 rows x 128 halfs = 4096 uint4) during the scan
        int t2 = tid - 128;
        #pragma unroll
        for (int i = 0; i < 32; i++) {
            int flat = i*128 + t2;
            int k = flat >> 4, ch = flat & 15;
            *(uint4*)&Wh[k*PB + ch*8] = *(const uint4*)&g_W2t[(size_t)k*HDIM + ch*8];
        }
    }
    __syncthreads();

    // GEMM2: out(128 x 128) = ys(128 x 256) @ W2^T, K=256
    float acc[2][8][4] = {};
    #pragma unroll
    for (int ks = 0; ks < 16; ks++) {
        int k0 = ks*16;
        uint32_t a[2][4], bfr[8][2];
        #pragma unroll
        for (int mf = 0; mf < 2; mf++)
            ldsm4(sY + ((wm*32 + mf*16 + arow)*PY + k0 + asel)*2, a[mf]);
        #pragma unroll
        for (int np = 0; np < 4; np++) {
            uint32_t rr[4];
            ldsm4t(sW + ((k0 + arow)*PB + wn*64 + np*16 + asel)*2, rr);
            bfr[np*2][0] = rr[0]; bfr[np*2][1] = rr[1];
            bfr[np*2+1][0] = rr[2]; bfr[np*2+1][1] = rr[3];
        }
        #pragma unroll
        for (int mf = 0; mf < 2; mf++)
            #pragma unroll
            for (int nf = 0; nf < 8; nf++)
                mma_f16(acc[mf][nf], a[mf], bfr[nf]);
    }

    #pragma unroll
    for (int mf = 0; mf < 2; mf++) {
        int row = bm + wm*32 + mf*16 + g;
        #pragma unroll
        for (int nf = 0; nf < 8; nf++) {
            int col = wn*64 + nf*8 + 2*t;
            float2 d0 = *(const float2*)&Dv[col];
            float2 x0 = *(const float2*)&x[(size_t)row*128 + col];
            float2 x1 = *(const float2*)&x[(size_t)(row+8)*128 + col];
            float2 o0 = make_float2(acc[mf][nf][0] + d0.x*x0.x, acc[mf][nf][1] + d0.y*x0.y);
            float2 o1 = make_float2(acc[mf][nf][2] + d0.x*x1.x, acc[mf][nf][3] + d0.y*x1.y);
            *(float2*)&outp[(size_t)row*128 + col]     = o0;
            *(float2*)&outp[(size_t)(row+8)*128 + col] = o1;
        }
    }
}

// ---------------- launch ------------------------------------------------------
extern "C" void kernel_launch(void* const* d_in, const int* in_sizes, int n_in,
                              void* d_out, int out_size) {
    const float* x  = (const float*)d_in[0];
    const float* Ad = (const float*)d_in[1];
    const float* Gd = (const float*)d_in[2];
    const float* dt = (const float*)d_in[3];
    const float* B  = (const float*)d_in[4];
    const float* C  = (const float*)d_in[5];
    const float* D  = (const float*)d_in[6];
    float* out = (float*)d_out;

    const int SMEM1 = 2 * 128 * PA * 2;                 // 69632
    const int SMEMF = 65536 + 67584 + 69632;            // 202752
    cudaFuncSetAttribute(gemm1_kernel, cudaFuncAttributeMaxDynamicSharedMemorySize, SMEM1);
    cudaFuncSetAttribute(fused_final_kernel, cudaFuncAttributeMaxDynamicSharedMemorySize, SMEMF);

    prep_kernel<<<1, 256>>>(Ad, Gd, dt, B, C);
    gemm1_kernel<<<dim3(2, MROWS/128), 256, SMEM1>>>(x);
    scan_carry_kernel<<<BSZ_, 128>>>();
    fused_final_kernel<<<dim3(NC, BSZ_), 256, SMEMF>>>(out, x, D);
}

// round 10
// speedup vs baseline: 3.1443x; 1.0548x over previous
#include <cuda_runtime.h>
#include <cuda_fp16.h>
#include <math.h>
#include <stdint.h>

#define BSZ_ 8
#define LEN_ 8192
#define PDIM 128
#define HDIM 128
#define CH 128
#define NC (LEN_/CH)          // 64
#define MROWS (BSZ_*LEN_)     // 65536
#define PA 136                // smem pitch (halfs) for K=128 tiles
#define PY 264                // smem pitch (halfs) for K=256 ys tile (33 uint4/row)
#define PB 136                // smem pitch (halfs) for W2 half-tile

// ---------------- scratch ----------------------------------------------------
__device__ __half2 g_Buh[(size_t)MROWS*PDIM];      // 32 MB Bu as half2 (row, p)
__device__ float4 g_csum[BSZ_*NC*PDIM];
__device__ float4 g_cin [BSZ_*NC*PDIM];
__device__ float4 g_M  [PDIM];
__device__ float2 g_c  [PDIM];
__device__ float4 g_Mp [PDIM];                     // M^CH
__device__ __half g_W1t[HDIM*2*PDIM];              // [k=h][n=2p+ri]
__device__ __half g_W2t[2*PDIM*HDIM];              // [k=2p+ri][n=h] (sign folded)

// ---------------- helpers ----------------------------------------------------
__device__ __forceinline__ uint32_t smem_u32(const void* p) {
    uint32_t a;
    asm("{ .reg .u64 t; cvta.to.shared.u64 t, %1; cvt.u32.u64 %0, t; }" : "=r"(a) : "l"(p));
    return a;
}
__device__ __forceinline__ void ldsm4(uint32_t addr, uint32_t* r) {
    asm volatile("ldmatrix.sync.aligned.m8n8.x4.shared.b16 {%0,%1,%2,%3}, [%4];"
                 : "=r"(r[0]), "=r"(r[1]), "=r"(r[2]), "=r"(r[3]) : "r"(addr));
}
__device__ __forceinline__ void ldsm4t(uint32_t addr, uint32_t* r) {
    asm volatile("ldmatrix.sync.aligned.m8n8.x4.trans.shared.b16 {%0,%1,%2,%3}, [%4];"
                 : "=r"(r[0]), "=r"(r[1]), "=r"(r[2]), "=r"(r[3]) : "r"(addr));
}
__device__ __forceinline__ void mma_f16(float* d, const uint32_t* a, const uint32_t* b) {
    asm volatile(
        "mma.sync.aligned.m16n8k16.row.col.f32.f16.f16.f32 "
        "{%0,%1,%2,%3}, {%4,%5,%6,%7}, {%8,%9}, {%0,%1,%2,%3};"
        : "+f"(d[0]), "+f"(d[1]), "+f"(d[2]), "+f"(d[3])
        : "r"(a[0]), "r"(a[1]), "r"(a[2]), "r"(a[3]), "r"(b[0]), "r"(b[1]));
}

// ---------------- prep -------------------------------------------------------
__global__ void prep_kernel(const float* __restrict__ Ad, const float* __restrict__ Gd,
                            const float* __restrict__ dtv,
                            const float* __restrict__ Bin, const float* __restrict__ Cin) {
    int tid = threadIdx.x;
    if (tid < PDIM) {
        int p = tid;
        float dts = 1.0f / (1.0f + expf(-dtv[p]));
        float A   = fmaxf(Ad[p], 0.0f);
        float G   = fmaxf(Gd[p], 0.0f);
        float dt2 = fmaxf(dts*dts, 1e-6f);
        float s   = sqrtf(1.0f + dts*G);
        float alo = (2.0f + dts*G - 2.0f*s) / dt2;
        float ahi = (2.0f + dts*G + 2.0f*s) / dt2;
        float Af  = fminf(fmaxf(A, alo), ahi);
        float S    = 1.0f + dts*G;
        float invS = 1.0f / S;
        float m11 = invS;
        float m12 = -dts*invS*Af;
        float m21 = dts*invS;
        float m22 = 1.0f - dts*dts*invS*Af;
        g_M[p] = make_float4(m11, m12, m21, m22);
        g_c[p] = make_float2(dts*invS, dts*dts*invS);
        float a = m11, b = m12, c = m21, d = m22;
        #pragma unroll
        for (int i = 0; i < 7; i++) {   // M^128
            float na = a*a + b*c;
            float nb = a*b + b*d;
            float nc = c*a + d*c;
            float nd = c*b + d*d;
            a = na; b = nb; c = nc; d = nd;
        }
        g_Mp[p] = make_float4(a, b, c, d);
    }
    for (int idx = tid; idx < HDIM*2*PDIM; idx += blockDim.x) {
        int h = idx / (2*PDIM), n = idx % (2*PDIM);
        int p = n >> 1, ri = n & 1;
        g_W1t[idx] = __float2half(Bin[((size_t)p*HDIM + h)*2 + ri]);
    }
    for (int idx = tid; idx < 2*PDIM*HDIM; idx += blockDim.x) {
        int k = idx / HDIM, h = idx % HDIM;
        float v = Cin[(size_t)h*2*PDIM + k];
        g_W2t[idx] = __float2half((k & 1) ? -v : v);
    }
}

// ---------------- GEMM1 (+fused chunk-partial scan), writes Bu as half --------
__global__ void __launch_bounds__(256, 2)
gemm1_kernel(const float* __restrict__ x) {
    extern __shared__ __align__(16) char smem[];
    __half* Ah = (__half*)smem;                    // [128][PA]
    __half* Bh = (__half*)(smem + 128*PA*2);       // [128][PA]
    float*  stage = (float*)smem;                  // alias, [128][130]
    uint32_t sA = smem_u32(Ah), sB = smem_u32(Bh);
    int tid = threadIdx.x, lane = tid & 31, wid = tid >> 5;
    int wm = wid >> 1, wn = wid & 1;
    int g = lane >> 2, t = lane & 3;
    int bm = blockIdx.y * 128, bn = blockIdx.x * 128;
    uint32_t arow = (uint32_t)(lane & 15);
    uint32_t asel = (uint32_t)((lane >> 4) * 8);

    #pragma unroll
    for (int i = 0; i < 16; i++) {
        int flat = i*256 + tid;
        int row = flat >> 5, c4 = flat & 31;
        float4 v = *(const float4*)&x[(size_t)(bm + row)*128 + c4*4];
        *(__half2*)&Ah[row*PA + c4*4]     = __floats2half2_rn(v.x, v.y);
        *(__half2*)&Ah[row*PA + c4*4 + 2] = __floats2half2_rn(v.z, v.w);
    }
    #pragma unroll
    for (int i = 0; i < 8; i++) {
        int flat = i*256 + tid;
        int k = flat >> 4, ch = flat & 15;
        *(uint4*)&Bh[k*PA + ch*8] = *(const uint4*)&g_W1t[(size_t)k*2*PDIM + bn + ch*8];
    }
    __syncthreads();

    float acc[2][8][4] = {};
    #pragma unroll
    for (int ks = 0; ks < 8; ks++) {
        int k0 = ks*16;
        uint32_t a[2][4], b[8][2];
        #pragma unroll
        for (int mf = 0; mf < 2; mf++)
            ldsm4(sA + ((wm*32 + mf*16 + arow)*PA + k0 + asel)*2, a[mf]);
        #pragma unroll
        for (int np = 0; np < 4; np++) {
            uint32_t r[4];
            ldsm4t(sB + ((k0 + arow)*PA + wn*64 + np*16 + asel)*2, r);
            b[np*2][0] = r[0]; b[np*2][1] = r[1];
            b[np*2+1][0] = r[2]; b[np*2+1][1] = r[3];
        }
        #pragma unroll
        for (int mf = 0; mf < 2; mf++)
            #pragma unroll
            for (int nf = 0; nf < 8; nf++)
                mma_f16(acc[mf][nf], a[mf], b[nf]);
    }

    // stage acc to smem (A/B tiles dead)
    __syncthreads();
    #pragma unroll
    for (int mf = 0; mf < 2; mf++) {
        int rl = wm*32 + mf*16 + g;
        #pragma unroll
        for (int nf = 0; nf < 8; nf++) {
            int cl = wn*64 + nf*8 + 2*t;
            *(float2*)&stage[rl*130 + cl]     = make_float2(acc[mf][nf][0], acc[mf][nf][1]);
            *(float2*)&stage[(rl+8)*130 + cl] = make_float2(acc[mf][nf][2], acc[mf][nf][3]);
        }
    }
    __syncthreads();

    // coalesced half2 write of Bu (this CTA covers p in [bn/2, bn/2+64))
    int pbase = bn >> 1;
    #pragma unroll
    for (int i = 0; i < 32; i++) {
        int flat = i*256 + tid;
        int row = flat >> 6, j = flat & 63;
        float2 v = *(float2*)&stage[row*130 + 2*j];
        g_Buh[(size_t)(bm + row)*PDIM + pbase + j] = __floats2half2_rn(v.x, v.y);
    }

    // fused chunk-partial scan (64 p per CTA)
    if (tid < 64) {
        int pg = pbase + tid;
        float4 Mv = g_M[pg];
        float2 cv = g_c[pg];
        float h1r = 0.f, h1i = 0.f, h2r = 0.f, h2i = 0.f;
        #pragma unroll 8
        for (int l = 0; l < CH; l++) {
            float2 bu = *(float2*)&stage[l*130 + 2*tid];
            float n1r = Mv.x*h1r + Mv.y*h2r + cv.x*bu.x;
            float n1i = Mv.x*h1i + Mv.y*h2i + cv.x*bu.y;
            float n2r = Mv.z*h1r + Mv.w*h2r + cv.y*bu.x;
            float n2i = Mv.z*h1i + Mv.w*h2i + cv.y*bu.y;
            h1r = n1r; h1i = n1i; h2r = n2r; h2i = n2i;
        }
        int b = blockIdx.y >> 6;
        int c = blockIdx.y & 63;
        g_csum[(b*NC + c)*PDIM + pg] = make_float4(h1r, h1i, h2r, h2i);
    }
}

// ---------------- carry: scan over chunks with M^CH (batch 16) ----------------
__global__ void scan_carry_kernel() {
    int p = threadIdx.x;
    int b = blockIdx.x;
    float4 Mp = g_Mp[p];
    float h1r = 0.f, h1i = 0.f, h2r = 0.f, h2i = 0.f;
    for (int c0 = 0; c0 < NC; c0 += 16) {
        float4 s[16];
        #pragma unroll
        for (int j = 0; j < 16; j++)
            s[j] = g_csum[(b*NC + c0 + j)*PDIM + p];
        #pragma unroll
        for (int j = 0; j < 16; j++) {
            g_cin[(b*NC + c0 + j)*PDIM + p] = make_float4(h1r, h1i, h2r, h2i);
            float n1r = Mp.x*h1r + Mp.y*h2r + s[j].x;
            float n1i = Mp.x*h1i + Mp.y*h2i + s[j].y;
            float n2r = Mp.z*h1r + Mp.w*h2r + s[j].z;
            float n2i = Mp.z*h1i + Mp.w*h2i + s[j].w;
            h1r = n1r; h1i = n1i; h2r = n2r; h2i = n2i;
        }
    }
}

// ---------------- fused final: scan chunk in SMEM + GEMM2 + D*x ---------------
// SMEM (100 KB -> 2 CTAs/SM): Ys [128][PY] half (67584B, holds Bu then ys in place)
//                             Wh [128][PB] half (34816B, W2 K-half, reloaded per phase)
__global__ void __launch_bounds__(256, 2)
fused_final_kernel(float* __restrict__ outp, const float* __restrict__ x,
                   const float* __restrict__ Dv) {
    extern __shared__ __align__(16) char smem[];
    __half* Ys = (__half*)smem;                          // 67584 B
    __half* Wh = (__half*)(smem + 67584);                // 34816 B
    uint32_t sY = smem_u32(Ys), sW = smem_u32(Wh);
    int tid = threadIdx.x, lane = tid & 31, wid = tid >> 5;
    int wm = wid >> 1, wn = wid & 1;
    int g = lane >> 2, t = lane & 3;
    int c = blockIdx.x, b = blockIdx.y;
    int bm = (b*NC + c) * CH;                            // global row base
    uint32_t arow = (uint32_t)(lane & 15);
    uint32_t asel = (uint32_t)((lane >> 4) * 8);

    // incoming state for this chunk (threads 0-127, one per p)
    float4 hin;
    if (tid < 128) hin = g_cin[(b*NC + c)*PDIM + tid];

    // load Bu chunk into Ys buffer: 128 rows x 32 uint4, pitch 33 uint4/row
    {
        const uint4* src = (const uint4*)&g_Buh[(size_t)bm*PDIM];
        uint4* dst = (uint4*)Ys;
        #pragma unroll
        for (int i = 0; i < 16; i++) {
            int flat = i*256 + tid;
            int l = flat >> 5, j = flat & 31;
            dst[l*33 + j] = src[flat];
        }
    }
    __syncthreads();

    if (tid < 128) {
        // serial scan from SMEM, overwrite bu with ys (half) in place
        int p = tid;
        float4 Mv = g_M[p];
        float2 cv = g_c[p];
        float h1r = hin.x, h1i = hin.y, h2r = hin.z, h2i = hin.w;
        #pragma unroll 8
        for (int l = 0; l < CH; l++) {
            __half2* slot = (__half2*)&Ys[l*PY + 2*p];
            float2 bu = __half22float2(*slot);
            float n1r = Mv.x*h1r + Mv.y*h2r + cv.x*bu.x;
            float n1i = Mv.x*h1i + Mv.y*h2i + cv.x*bu.y;
            float n2r = Mv.z*h1r + Mv.w*h2r + cv.y*bu.x;
            float n2i = Mv.z*h1i + Mv.w*h2i + cv.y*bu.y;
            h1r = n1r; h1i = n1i; h2r = n2r; h2i = n2i;
            *slot = __floats2half2_rn(h2r, h2i);
        }
    } else {
        // warps 4-7: load W2 K-half 0 (128 rows x 128 halfs = 2048 uint4)
        int t2 = tid - 128;
        #pragma unroll
        for (int i = 0; i < 16; i++) {
            int flat = i*128 + t2;
            int k = flat >> 4, ch = flat & 15;
            *(uint4*)&Wh[k*PB + ch*8] = *(const uint4*)&g_W2t[(size_t)k*HDIM + ch*8];
        }
    }
    __syncthreads();

    // GEMM2: out(128 x 128) = ys(128 x 256) @ W2^T, K=256 in two K=128 phases
    float acc[2][8][4] = {};
    #pragma unroll
    for (int r = 0; r < 2; r++) {
        if (r) {
            __syncthreads();   // phase-0 mma reads of Wh complete
            #pragma unroll
            for (int i = 0; i < 8; i++) {
                int flat = i*256 + tid;
                int k = flat >> 4, ch = flat & 15;
                *(uint4*)&Wh[k*PB + ch*8] =
                    *(const uint4*)&g_W2t[(size_t)(128 + k)*HDIM + ch*8];
            }
            __syncthreads();
        }
        #pragma unroll
        for (int ks = 0; ks < 8; ks++) {
            int k0 = ks*16;
            uint32_t a[2][4], bfr[8][2];
            #pragma unroll
            for (int mf = 0; mf < 2; mf++)
                ldsm4(sY + ((wm*32 + mf*16 + arow)*PY + r*128 + k0 + asel)*2, a[mf]);
            #pragma unroll
            for (int np = 0; np < 4; np++) {
                uint32_t rr[4];
                ldsm4t(sW + ((k0 + arow)*PB + wn*64 + np*16 + asel)*2, rr);
                bfr[np*2][0] = rr[0]; bfr[np*2][1] = rr[1];
                bfr[np*2+1][0] = rr[2]; bfr[np*2+1][1] = rr[3];
            }
            #pragma unroll
            for (int mf = 0; mf < 2; mf++)
                #pragma unroll
                for (int nf = 0; nf < 8; nf++)
                    mma_f16(acc[mf][nf], a[mf], bfr[nf]);
        }
    }

    #pragma unroll
    for (int mf = 0; mf < 2; mf++) {
        int row = bm + wm*32 + mf*16 + g;
        #pragma unroll
        for (int nf = 0; nf < 8; nf++) {
            int col = wn*64 + nf*8 + 2*t;
            float2 d0 = *(const float2*)&Dv[col];
            float2 x0 = *(const float2*)&x[(size_t)row*128 + col];
            float2 x1 = *(const float2*)&x[(size_t)(row+8)*128 + col];
            float2 o0 = make_float2(acc[mf][nf][0] + d0.x*x0.x, acc[mf][nf][1] + d0.y*x0.y);
            float2 o1 = make_float2(acc[mf][nf][2] + d0.x*x1.x, acc[mf][nf][3] + d0.y*x1.y);
            *(float2*)&outp[(size_t)row*128 + col]     = o0;
            *(float2*)&outp[(size_t)(row+8)*128 + col] = o1;
        }
    }
}

// ---------------- launch ------------------------------------------------------
extern "C" void kernel_launch(void* const* d_in, const int* in_sizes, int n_in,
                              void* d_out, int out_size) {
    const float* x  = (const float*)d_in[0];
    const float* Ad = (const float*)d_in[1];
    const float* Gd = (const float*)d_in[2];
    const float* dt = (const float*)d_in[3];
    const float* B  = (const float*)d_in[4];
    const float* C  = (const float*)d_in[5];
    const float* D  = (const float*)d_in[6];
    float* out = (float*)d_out;

    const int SMEM1 = 2 * 128 * PA * 2;                 // 69632
    const int SMEMF = 67584 + 34816;                    // 102400
    cudaFuncSetAttribute(gemm1_kernel, cudaFuncAttributeMaxDynamicSharedMemorySize, SMEM1);
    cudaFuncSetAttribute(fused_final_kernel, cudaFuncAttributeMaxDynamicSharedMemorySize, SMEMF);

    prep_kernel<<<1, 256>>>(Ad, Gd, dt, B, C);
    gemm1_kernel<<<dim3(2, MROWS/128), 256, SMEM1>>>(x);
    scan_carry_kernel<<<BSZ_, 128>>>();
    fused_final_kernel<<<dim3(NC, BSZ_), 256, SMEMF>>>(out, x, D);
}

// round 11
// speedup vs baseline: 4.2098x; 1.3389x over previous
#include <cuda_runtime.h>
#include <cuda_fp16.h>
#include <math.h>
#include <stdint.h>

#define BSZ_ 8
#define LEN_ 8192
#define PDIM 128
#define HDIM 128
#define CH 64
#define NC (LEN_/CH)          // 128
#define MROWS (BSZ_*LEN_)     // 65536
#define PA 136                // smem pitch (halfs) for K=128 tiles
#define PY 264                // smem pitch (halfs) for K=256 ys tile (33 uint4/row)
#define PB 136                // smem pitch (halfs) for W2 half-tile

// ---------------- scratch ----------------------------------------------------
__device__ __half2 g_Buh[(size_t)MROWS*PDIM];      // 32 MB Bu as half2 (row, p)
__device__ float4 g_csum[BSZ_*NC*PDIM];            // 2 MB
__device__ float4 g_cin [BSZ_*NC*PDIM];            // 2 MB
__device__ float4 g_M  [PDIM];
__device__ float2 g_c  [PDIM];
__device__ float4 g_Mp [PDIM];                     // M^CH
__device__ __half g_W1t[HDIM*2*PDIM];              // [k=h][n=2p+ri]
__device__ __half g_W2t[2*PDIM*HDIM];              // [k=2p+ri][n=h] (sign folded)

// ---------------- helpers ----------------------------------------------------
__device__ __forceinline__ uint32_t smem_u32(const void* p) {
    uint32_t a;
    asm("{ .reg .u64 t; cvta.to.shared.u64 t, %1; cvt.u32.u64 %0, t; }" : "=r"(a) : "l"(p));
    return a;
}
__device__ __forceinline__ void ldsm4(uint32_t addr, uint32_t* r) {
    asm volatile("ldmatrix.sync.aligned.m8n8.x4.shared.b16 {%0,%1,%2,%3}, [%4];"
                 : "=r"(r[0]), "=r"(r[1]), "=r"(r[2]), "=r"(r[3]) : "r"(addr));
}
__device__ __forceinline__ void ldsm4t(uint32_t addr, uint32_t* r) {
    asm volatile("ldmatrix.sync.aligned.m8n8.x4.trans.shared.b16 {%0,%1,%2,%3}, [%4];"
                 : "=r"(r[0]), "=r"(r[1]), "=r"(r[2]), "=r"(r[3]) : "r"(addr));
}
__device__ __forceinline__ void mma_f16(float* d, const uint32_t* a, const uint32_t* b) {
    asm volatile(
        "mma.sync.aligned.m16n8k16.row.col.f32.f16.f16.f32 "
        "{%0,%1,%2,%3}, {%4,%5,%6,%7}, {%8,%9}, {%0,%1,%2,%3};"
        : "+f"(d[0]), "+f"(d[1]), "+f"(d[2]), "+f"(d[3])
        : "r"(a[0]), "r"(a[1]), "r"(a[2]), "r"(a[3]), "r"(b[0]), "r"(b[1]));
}

// ---------------- prep (parallel: 32 blocks) ----------------------------------
__global__ void prep_kernel(const float* __restrict__ Ad, const float* __restrict__ Gd,
                            const float* __restrict__ dtv,
                            const float* __restrict__ Bin, const float* __restrict__ Cin) {
    int tid = threadIdx.x;
    int gtid = blockIdx.x * blockDim.x + tid;
    int gstride = gridDim.x * blockDim.x;
    if (blockIdx.x == 0 && tid < PDIM) {
        int p = tid;
        float dts = 1.0f / (1.0f + expf(-dtv[p]));
        float A   = fmaxf(Ad[p], 0.0f);
        float G   = fmaxf(Gd[p], 0.0f);
        float dt2 = fmaxf(dts*dts, 1e-6f);
        float s   = sqrtf(1.0f + dts*G);
        float alo = (2.0f + dts*G - 2.0f*s) / dt2;
        float ahi = (2.0f + dts*G + 2.0f*s) / dt2;
        float Af  = fminf(fmaxf(A, alo), ahi);
        float S    = 1.0f + dts*G;
        float invS = 1.0f / S;
        float m11 = invS;
        float m12 = -dts*invS*Af;
        float m21 = dts*invS;
        float m22 = 1.0f - dts*dts*invS*Af;
        g_M[p] = make_float4(m11, m12, m21, m22);
        g_c[p] = make_float2(dts*invS, dts*dts*invS);
        float a = m11, b = m12, c = m21, d = m22;
        #pragma unroll
        for (int i = 0; i < 6; i++) {   // M^64
            float na = a*a + b*c;
            float nb = a*b + b*d;
            float nc = c*a + d*c;
            float nd = c*b + d*d;
            a = na; b = nb; c = nc; d = nd;
        }
        g_Mp[p] = make_float4(a, b, c, d);
    }
    for (int idx = gtid; idx < HDIM*2*PDIM; idx += gstride) {
        int h = idx / (2*PDIM), n = idx % (2*PDIM);
        int p = n >> 1, ri = n & 1;
        g_W1t[idx] = __float2half(Bin[((size_t)p*HDIM + h)*2 + ri]);
    }
    for (int idx = gtid; idx < 2*PDIM*HDIM; idx += gstride) {
        int k = idx / HDIM, h = idx % HDIM;
        float v = Cin[(size_t)h*2*PDIM + k];
        g_W2t[idx] = __float2half((k & 1) ? -v : v);
    }
}

// ---------------- GEMM1 (+fused chunk-partial scan), writes Bu as half --------
// CTA tile 128 rows = 2 chunks of CH=64
__global__ void __launch_bounds__(256, 2)
gemm1_kernel(const float* __restrict__ x) {
    extern __shared__ __align__(16) char smem[];
    __half* Ah = (__half*)smem;                    // [128][PA]
    __half* Bh = (__half*)(smem + 128*PA*2);       // [128][PA]
    float*  stage = (float*)smem;                  // alias, [128][130]
    uint32_t sA = smem_u32(Ah), sB = smem_u32(Bh);
    int tid = threadIdx.x, lane = tid & 31, wid = tid >> 5;
    int wm = wid >> 1, wn = wid & 1;
    int g = lane >> 2, t = lane & 3;
    int bm = blockIdx.y * 128, bn = blockIdx.x * 128;
    uint32_t arow = (uint32_t)(lane & 15);
    uint32_t asel = (uint32_t)((lane >> 4) * 8);

    #pragma unroll
    for (int i = 0; i < 16; i++) {
        int flat = i*256 + tid;
        int row = flat >> 5, c4 = flat & 31;
        float4 v = *(const float4*)&x[(size_t)(bm + row)*128 + c4*4];
        *(__half2*)&Ah[row*PA + c4*4]     = __floats2half2_rn(v.x, v.y);
        *(__half2*)&Ah[row*PA + c4*4 + 2] = __floats2half2_rn(v.z, v.w);
    }
    #pragma unroll
    for (int i = 0; i < 8; i++) {
        int flat = i*256 + tid;
        int k = flat >> 4, ch = flat & 15;
        *(uint4*)&Bh[k*PA + ch*8] = *(const uint4*)&g_W1t[(size_t)k*2*PDIM + bn + ch*8];
    }
    __syncthreads();

    float acc[2][8][4] = {};
    #pragma unroll
    for (int ks = 0; ks < 8; ks++) {
        int k0 = ks*16;
        uint32_t a[2][4], b[8][2];
        #pragma unroll
        for (int mf = 0; mf < 2; mf++)
            ldsm4(sA + ((wm*32 + mf*16 + arow)*PA + k0 + asel)*2, a[mf]);
        #pragma unroll
        for (int np = 0; np < 4; np++) {
            uint32_t r[4];
            ldsm4t(sB + ((k0 + arow)*PA + wn*64 + np*16 + asel)*2, r);
            b[np*2][0] = r[0]; b[np*2][1] = r[1];
            b[np*2+1][0] = r[2]; b[np*2+1][1] = r[3];
        }
        #pragma unroll
        for (int mf = 0; mf < 2; mf++)
            #pragma unroll
            for (int nf = 0; nf < 8; nf++)
                mma_f16(acc[mf][nf], a[mf], b[nf]);
    }

    // stage acc to smem (A/B tiles dead)
    __syncthreads();
    #pragma unroll
    for (int mf = 0; mf < 2; mf++) {
        int rl = wm*32 + mf*16 + g;
        #pragma unroll
        for (int nf = 0; nf < 8; nf++) {
            int cl = wn*64 + nf*8 + 2*t;
            *(float2*)&stage[rl*130 + cl]     = make_float2(acc[mf][nf][0], acc[mf][nf][1]);
            *(float2*)&stage[(rl+8)*130 + cl] = make_float2(acc[mf][nf][2], acc[mf][nf][3]);
        }
    }
    __syncthreads();

    // coalesced half2 write of Bu (this CTA covers p in [bn/2, bn/2+64))
    int pbase = bn >> 1;
    #pragma unroll
    for (int i = 0; i < 32; i++) {
        int flat = i*256 + tid;
        int row = flat >> 6, j = flat & 63;
        float2 v = *(float2*)&stage[row*130 + 2*j];
        g_Buh[(size_t)(bm + row)*PDIM + pbase + j] = __floats2half2_rn(v.x, v.y);
    }

    // fused chunk-partial scans: 2 chunks of 64, threads 0-127
    if (tid < 128) {
        int pl = tid & 63;             // local p (column pair)
        int sub = tid >> 6;            // which 64-row chunk
        int pg = pbase + pl;
        float4 Mv = g_M[pg];
        float2 cv = g_c[pg];
        float h1r = 0.f, h1i = 0.f, h2r = 0.f, h2i = 0.f;
        #pragma unroll 8
        for (int l = 0; l < CH; l++) {
            float2 bu = *(float2*)&stage[(sub*64 + l)*130 + 2*pl];
            float n1r = Mv.x*h1r + Mv.y*h2r + cv.x*bu.x;
            float n1i = Mv.x*h1i + Mv.y*h2i + cv.x*bu.y;
            float n2r = Mv.z*h1r + Mv.w*h2r + cv.y*bu.x;
            float n2i = Mv.z*h1i + Mv.w*h2i + cv.y*bu.y;
            h1r = n1r; h1i = n1i; h2r = n2r; h2i = n2i;
        }
        int b = blockIdx.y >> 6;                       // 64 row-blocks per batch
        int cc = (blockIdx.y & 63)*2 + sub;            // chunk index within batch
        g_csum[(b*NC + cc)*PDIM + pg] = make_float4(h1r, h1i, h2r, h2i);
    }
}

// ---------------- carry: scan over NC=128 chunks with M^CH (batch 16) ---------
__global__ void scan_carry_kernel() {
    int p = threadIdx.x;
    int b = blockIdx.x;
    float4 Mp = g_Mp[p];
    float h1r = 0.f, h1i = 0.f, h2r = 0.f, h2i = 0.f;
    for (int c0 = 0; c0 < NC; c0 += 16) {
        float4 s[16];
        #pragma unroll
        for (int j = 0; j < 16; j++)
            s[j] = g_csum[(b*NC + c0 + j)*PDIM + p];
        #pragma unroll
        for (int j = 0; j < 16; j++) {
            g_cin[(b*NC + c0 + j)*PDIM + p] = make_float4(h1r, h1i, h2r, h2i);
            float n1r = Mp.x*h1r + Mp.y*h2r + s[j].x;
            float n1i = Mp.x*h1i + Mp.y*h2i + s[j].y;
            float n2r = Mp.z*h1r + Mp.w*h2r + s[j].z;
            float n2i = Mp.z*h1i + Mp.w*h2i + s[j].w;
            h1r = n1r; h1i = n1i; h2r = n2r; h2i = n2i;
        }
    }
}

// ---------------- fused final: M=64 tile, scan + GEMM2 + D*x ------------------
// SMEM (68.6 KB -> 3 CTAs/SM): Ys [64][PY] half (33792B, Bu then ys in place)
//                              Wh [128][PB] half (34816B, W2 K-half)
__global__ void __launch_bounds__(256, 3)
fused_final_kernel(float* __restrict__ outp, const float* __restrict__ x,
                   const float* __restrict__ Dv) {
    extern __shared__ __align__(16) char smem[];
    __half* Ys = (__half*)smem;                          // 33792 B
    __half* Wh = (__half*)(smem + 33792);                // 34816 B
    uint32_t sY = smem_u32(Ys), sW = smem_u32(Wh);
    int tid = threadIdx.x, lane = tid & 31, wid = tid >> 5;
    int wm = wid >> 1, wn = wid & 1;
    int g = lane >> 2, t = lane & 3;
    int c = blockIdx.x, b = blockIdx.y;
    int bm = b*LEN_ + c*CH;                              // global row base (64 rows)
    uint32_t arow = (uint32_t)(lane & 15);
    uint32_t asel = (uint32_t)((lane >> 4) * 8);

    // incoming state for this chunk (threads 0-127, one per p)
    float4 hin;
    if (tid < 128) hin = g_cin[(b*NC + c)*PDIM + tid];

    // load Bu chunk into Ys buffer: 64 rows x 32 uint4, pitch 33 uint4/row
    {
        const uint4* src = (const uint4*)&g_Buh[(size_t)bm*PDIM];
        uint4* dst = (uint4*)Ys;
        #pragma unroll
        for (int i = 0; i < 8; i++) {
            int flat = i*256 + tid;
            int l = flat >> 5, j = flat & 31;
            dst[l*33 + j] = src[flat];
        }
    }
    __syncthreads();

    if (tid < 128) {
        // serial scan from SMEM (64 steps), overwrite bu with ys (half) in place
        int p = tid;
        float4 Mv = g_M[p];
        float2 cv = g_c[p];
        float h1r = hin.x, h1i = hin.y, h2r = hin.z, h2i = hin.w;
        #pragma unroll 8
        for (int l = 0; l < CH; l++) {
            __half2* slot = (__half2*)&Ys[l*PY + 2*p];
            float2 bu = __half22float2(*slot);
            float n1r = Mv.x*h1r + Mv.y*h2r + cv.x*bu.x;
            float n1i = Mv.x*h1i + Mv.y*h2i + cv.x*bu.y;
            float n2r = Mv.z*h1r + Mv.w*h2r + cv.y*bu.x;
            float n2i = Mv.z*h1i + Mv.w*h2i + cv.y*bu.y;
            h1r = n1r; h1i = n1i; h2r = n2r; h2i = n2i;
            *slot = __floats2half2_rn(h2r, h2i);
        }
    } else {
        // warps 4-7: load W2 K-half 0 (128 rows x 128 halfs = 2048 uint4)
        int t2 = tid - 128;
        #pragma unroll
        for (int i = 0; i < 16; i++) {
            int flat = i*128 + t2;
            int k = flat >> 4, ch = flat & 15;
            *(uint4*)&Wh[k*PB + ch*8] = *(const uint4*)&g_W2t[(size_t)k*HDIM + ch*8];
        }
    }
    __syncthreads();

    // GEMM2: out(64 x 128) = ys(64 x 256) @ W2^T, K=256 in two K=128 phases
    float acc[8][4] = {};
    #pragma unroll
    for (int r = 0; r < 2; r++) {
        if (r) {
            __syncthreads();   // phase-0 mma reads of Wh complete
            #pragma unroll
            for (int i = 0; i < 8; i++) {
                int flat = i*256 + tid;
                int k = flat >> 4, ch = flat & 15;
                *(uint4*)&Wh[k*PB + ch*8] =
                    *(const uint4*)&g_W2t[(size_t)(128 + k)*HDIM + ch*8];
            }
            __syncthreads();
        }
        #pragma unroll
        for (int ks = 0; ks < 8; ks++) {
            int k0 = ks*16;
            uint32_t a[4], bfr[8][2];
            ldsm4(sY + ((wm*16 + arow)*PY + r*128 + k0 + asel)*2, a);
            #pragma unroll
            for (int np = 0; np < 4; np++) {
                uint32_t rr[4];
                ldsm4t(sW + ((k0 + arow)*PB + wn*64 + np*16 + asel)*2, rr);
                bfr[np*2][0] = rr[0]; bfr[np*2][1] = rr[1];
                bfr[np*2+1][0] = rr[2]; bfr[np*2+1][1] = rr[3];
            }
            #pragma unroll
            for (int nf = 0; nf < 8; nf++)
                mma_f16(acc[nf], a, bfr[nf]);
        }
    }

    {
        int row = bm + wm*16 + g;
        #pragma unroll
        for (int nf = 0; nf < 8; nf++) {
            int col = wn*64 + nf*8 + 2*t;
            float2 d0 = *(const float2*)&Dv[col];
            float2 x0 = *(const float2*)&x[(size_t)row*128 + col];
            float2 x1 = *(const float2*)&x[(size_t)(row+8)*128 + col];
            float2 o0 = make_float2(acc[nf][0] + d0.x*x0.x, acc[nf][1] + d0.y*x0.y);
            float2 o1 = make_float2(acc[nf][2] + d0.x*x1.x, acc[nf][3] + d0.y*x1.y);
            *(float2*)&outp[(size_t)row*128 + col]     = o0;
            *(float2*)&outp[(size_t)(row+8)*128 + col] = o1;
        }
    }
}

// ---------------- launch ------------------------------------------------------
extern "C" void kernel_launch(void* const* d_in, const int* in_sizes, int n_in,
                              void* d_out, int out_size) {
    const float* x  = (const float*)d_in[0];
    const float* Ad = (const float*)d_in[1];
    const float* Gd = (const float*)d_in[2];
    const float* dt = (const float*)d_in[3];
    const float* B  = (const float*)d_in[4];
    const float* C  = (const float*)d_in[5];
    const float* D  = (const float*)d_in[6];
    float* out = (float*)d_out;

    const int SMEM1 = 2 * 128 * PA * 2;                 // 69632
    const int SMEMF = 33792 + 34816;                    // 68608
    cudaFuncSetAttribute(gemm1_kernel, cudaFuncAttributeMaxDynamicSharedMemorySize, SMEM1);
    cudaFuncSetAttribute(fused_final_kernel, cudaFuncAttributeMaxDynamicSharedMemorySize, SMEMF);

    prep_kernel<<<32, 256>>>(Ad, Gd, dt, B, C);
    gemm1_kernel<<<dim3(2, MROWS/128), 256, SMEM1>>>(x);
    scan_carry_kernel<<<BSZ_, 128>>>();
    fused_final_kernel<<<dim3(NC, BSZ_), 256, SMEMF>>>(out, x, D);
}